// round 10
// baseline (speedup 1.0000x reference)
#include <cuda_runtime.h>
#include <cuda_fp16.h>
#include <cstdint>

#define N_NODES   100000
#define N_EDGES   600000
#define D_FEAT    128
#define NOUT      128          // 64 (P = h@Wu^T + b) + 64 (Q = h@Wv^T)
#define GRIDX     148
#define TILE_M    64
#define TILES     1563         // ceil(N_NODES / 64)

// ---------------------------------------------------------------------------
// Device scratch: per-node projections in fp16.
// ---------------------------------------------------------------------------
__device__ __half g_PQh[(size_t)N_NODES * NOUT];

// Swizzled byte offset inside a [row][k] fp16 tile with 256B row stride.
__device__ __forceinline__ uint32_t tswz(int row, int kbyte) {
    return (uint32_t)(row * 256 + (kbyte ^ ((row & 7) << 4)));
}

__device__ __forceinline__ uint32_t smem_u32(const void* p) {
    uint32_t a;
    asm("{ .reg .u64 t; cvta.to.shared.u64 t, %1; cvt.u32.u64 %0, t; }" : "=r"(a) : "l"(p));
    return a;
}

__device__ __forceinline__ void ldsm_x4(uint32_t addr, uint32_t* r) {
    asm volatile("ldmatrix.sync.aligned.m8n8.x4.shared.b16 {%0,%1,%2,%3}, [%4];"
                 : "=r"(r[0]), "=r"(r[1]), "=r"(r[2]), "=r"(r[3]) : "r"(addr));
}
__device__ __forceinline__ void ldsm_x2(uint32_t addr, uint32_t* r) {
    asm volatile("ldmatrix.sync.aligned.m8n8.x2.shared.b16 {%0,%1}, [%2];"
                 : "=r"(r[0]), "=r"(r[1]) : "r"(addr));
}
__device__ __forceinline__ void mma_f16(float* c, const uint32_t* a, const uint32_t* b) {
    asm volatile("mma.sync.aligned.m16n8k16.row.col.f32.f16.f16.f32 "
                 "{%0,%1,%2,%3}, {%4,%5,%6,%7}, {%8,%9}, {%0,%1,%2,%3};"
                 : "+f"(c[0]), "+f"(c[1]), "+f"(c[2]), "+f"(c[3])
                 : "r"(a[0]), "r"(a[1]), "r"(a[2]), "r"(a[3]), "r"(b[0]), "r"(b[1]));
}

// Convert float4 -> 2x half2 and store 8B at swizzled offset (B staging).
__device__ __forceinline__ void f16_store(char* smem, uint32_t base,
                                          int row, int k4, float4 v) {
    __half2 h0 = __floats2half2_rn(v.x, v.y);
    __half2 h1 = __floats2half2_rn(v.z, v.w);
    uint32_t off = tswz(row, k4 * 8);
    *(uint2*)(smem + base + off) = make_uint2(*(uint32_t*)&h0, *(uint32_t*)&h1);
}

// Convert two consecutive float4 -> 4x half2, single STS.128 (A staging).
// Requires k4 even so the 16B destination chunk is swizzle-aligned.
__device__ __forceinline__ void f16_store2(char* smem, uint32_t base,
                                           int row, int k4, float4 v0, float4 v1) {
    __half2 a0 = __floats2half2_rn(v0.x, v0.y);
    __half2 a1 = __floats2half2_rn(v0.z, v0.w);
    __half2 a2 = __floats2half2_rn(v1.x, v1.y);
    __half2 a3 = __floats2half2_rn(v1.z, v1.w);
    uint32_t off = tswz(row, k4 * 8);
    *(uint4*)(smem + base + off) = make_uint4(*(uint32_t*)&a0, *(uint32_t*)&a1,
                                              *(uint32_t*)&a2, *(uint32_t*)&a3);
}

// ---------------------------------------------------------------------------
// Smem: B once (32 KB), A double-buffered (2 x 16 KB). 64 KB total.
// ---------------------------------------------------------------------------
#define SM_B     0u
#define SM_A0    32768u
#define SM_A1    49152u
#define SM_TOTAL 65536

// ---------------------------------------------------------------------------
// Kernel 1: persistent HMMA GEMM, fp16 single-pass, fp32 accumulate.
// 148 CTAs x 256 threads, 64x128 tiles (wave-balanced), paired STS.128 staging,
// register prefetch of the next tile, fast-path full-tile epilogue.
// Warp (wm 0-1: 32-row half, wn 0-3: 32-col strip) -> 32x32 per warp.
// ---------------------------------------------------------------------------
__global__ void __launch_bounds__(256, 1)
gemm_kernel(const float* __restrict__ h, const float* __restrict__ W,
            const float* __restrict__ b) {
    extern __shared__ char smem[];
    const uint32_t sm_base = smem_u32(smem);
    const int tid = threadIdx.x;
    const int wid = tid >> 5;
    const int lid = tid & 31;

    // ---- Stage B once (128 x 128 fp16)
    #pragma unroll
    for (int i = tid; i < 4096; i += 256) {
        int j  = i >> 5;
        int k4 = i & 31;
        const float* wp = (j < 64) ? &W[j * 256 + k4 * 4]
                                   : &W[(j - 64) * 256 + 128 + k4 * 4];
        f16_store(smem, SM_B, j, k4, *(const float4*)wp);
    }

    // ---- Stage A first tile into buf0 (paired: 4 iters x 2 float4)
    {
        const int node0 = blockIdx.x * TILE_M;
        #pragma unroll
        for (int i = 0; i < 4; ++i) {
            int p  = tid + i * 256;        // pair index 0..1023
            int m  = p >> 4;               // 0..63
            int k4 = (p & 15) * 2;         // even
            int gm = node0 + m; if (gm >= N_NODES) gm = N_NODES - 1;
            const float4* hp = (const float4*)&h[(size_t)gm * D_FEAT + k4 * 4];
            f16_store2(smem, SM_A0, m, k4, hp[0], hp[1]);
        }
    }
    __syncthreads();

    // ---- Per-thread constants
    const int wm = wid & 1;      // 32-row half
    const int wn = wid >> 1;     // 32-col strip
    const int a_row = (lid & 7) + ((lid >> 3) & 1) * 8;
    const int a_kb  = (lid >> 4) * 16;
    const int b_row = (lid & 7);
    const int b_kb  = ((lid >> 3) & 1) * 16;
    const int xora  = (lid & 7) << 4;
    const int trow = lid >> 2;
    const int tcol = (lid & 3) * 2;

    float2 bias2[4];
    #pragma unroll
    for (int nf = 0; nf < 4; ++nf) {
        int col = wn * 32 + nf * 8 + tcol;
        bias2[nf] = (col < 64) ? *(const float2*)&b[col] : make_float2(0.f, 0.f);
    }

    int pb = 0;
    for (int t = blockIdx.x; t < TILES; t += GRIDX, pb ^= 1) {
        const int tn = t + GRIDX;
        const bool pre = (tn < TILES);

        // ---- (1) Prefetch next tile's h into registers (4 float4-pairs)
        float4 rg[8];
        if (pre) {
            const int node0n = tn * TILE_M;
            if (node0n + TILE_M <= N_NODES) {
                #pragma unroll
                for (int i = 0; i < 4; ++i) {
                    int p  = tid + i * 256;
                    int m  = p >> 4;
                    int k4 = (p & 15) * 2;
                    const float4* hp = (const float4*)&h[(size_t)(node0n + m) * D_FEAT + k4 * 4];
                    rg[i * 2]     = hp[0];
                    rg[i * 2 + 1] = hp[1];
                }
            } else {
                #pragma unroll
                for (int i = 0; i < 4; ++i) {
                    int p  = tid + i * 256;
                    int m  = p >> 4;
                    int k4 = (p & 15) * 2;
                    int gm = node0n + m; if (gm >= N_NODES) gm = N_NODES - 1;
                    const float4* hp = (const float4*)&h[(size_t)gm * D_FEAT + k4 * 4];
                    rg[i * 2]     = hp[0];
                    rg[i * 2 + 1] = hp[1];
                }
            }
        }

        // ---- (2) MMA mainloop on buffer pb
        const uint32_t abase = sm_base + (pb ? SM_A1 : SM_A0);
        float acc[2][4][4];
        #pragma unroll
        for (int mf = 0; mf < 2; ++mf)
            #pragma unroll
            for (int nf = 0; nf < 4; ++nf)
                #pragma unroll
                for (int i = 0; i < 4; ++i) acc[mf][nf][i] = 0.0f;

        #pragma unroll
        for (int ks = 0; ks < 8; ++ks) {
            uint32_t af[2][4], bf[4][2];
            const uint32_t akoff = (uint32_t)((ks * 32 + a_kb) ^ xora);
            const uint32_t bkoff = (uint32_t)((ks * 32 + b_kb) ^ xora);
            #pragma unroll
            for (int mf = 0; mf < 2; ++mf) {
                uint32_t ro = (uint32_t)((wm * 32 + mf * 16 + a_row) * 256) + akoff;
                ldsm_x4(abase + ro, af[mf]);
            }
            #pragma unroll
            for (int nf = 0; nf < 4; ++nf) {
                uint32_t ro = (uint32_t)((wn * 32 + nf * 8 + b_row) * 256) + bkoff;
                ldsm_x2(sm_base + SM_B + ro, bf[nf]);
            }
            #pragma unroll
            for (int mf = 0; mf < 2; ++mf)
                #pragma unroll
                for (int nf = 0; nf < 4; ++nf)
                    mma_f16(acc[mf][nf], af[mf], bf[nf]);
        }

        // ---- (3) Convert + store prefetched tile into the other buffer
        if (pre) {
            char* obuf = smem + (pb ? SM_A0 : SM_A1);
            #pragma unroll
            for (int i = 0; i < 4; ++i) {
                int p  = tid + i * 256;
                int m  = p >> 4;
                int k4 = (p & 15) * 2;
                f16_store2(obuf, 0u, m, k4, rg[i * 2], rg[i * 2 + 1]);
            }
        }

        // ---- (4) Epilogue: bias + fp16 store to PQ (fast path for full tiles)
        const int node0 = t * TILE_M;
        if (node0 + TILE_M <= N_NODES) {
            #pragma unroll
            for (int mf = 0; mf < 2; ++mf) {
                const int node_a = node0 + wm * 32 + mf * 16 + trow;
                #pragma unroll
                for (int nf = 0; nf < 4; ++nf) {
                    const int col = wn * 32 + nf * 8 + tcol;
                    __half2 h0 = __floats2half2_rn(acc[mf][nf][0] + bias2[nf].x,
                                                   acc[mf][nf][1] + bias2[nf].y);
                    __half2 h1 = __floats2half2_rn(acc[mf][nf][2] + bias2[nf].x,
                                                   acc[mf][nf][3] + bias2[nf].y);
                    *(__half2*)&g_PQh[(size_t)node_a * NOUT + col] = h0;
                    *(__half2*)&g_PQh[(size_t)(node_a + 8) * NOUT + col] = h1;
                }
            }
        } else {
            #pragma unroll
            for (int mf = 0; mf < 2; ++mf) {
                const int node_a = node0 + wm * 32 + mf * 16 + trow;
                const int node_b = node_a + 8;
                #pragma unroll
                for (int nf = 0; nf < 4; ++nf) {
                    const int col = wn * 32 + nf * 8 + tcol;
                    if (node_a < N_NODES) {
                        __half2 hv = __floats2half2_rn(acc[mf][nf][0] + bias2[nf].x,
                                                       acc[mf][nf][1] + bias2[nf].y);
                        *(__half2*)&g_PQh[(size_t)node_a * NOUT + col] = hv;
                    }
                    if (node_b < N_NODES) {
                        __half2 hv = __floats2half2_rn(acc[mf][nf][2] + bias2[nf].x,
                                                       acc[mf][nf][3] + bias2[nf].y);
                        *(__half2*)&g_PQh[(size_t)node_b * NOUT + col] = hv;
                    }
                }
            }
        }
        __syncthreads();
    }
}

// ---------------------------------------------------------------------------
// Kernel 2: gather-add, 2 edges per thread (R6 formulation — best measured).
// out[e][c] = PQh[src[e]][c] + PQh[dst[e]][64+c]
// ---------------------------------------------------------------------------
__global__ void __launch_bounds__(256)
gather_kernel(const int* __restrict__ src, const int* __restrict__ dst,
              float* __restrict__ out) {
    int t = blockIdx.x * blockDim.x + threadIdx.x;
    if (t >= (N_EDGES / 2) * 8) return;
    const int ep = t >> 3;
    const int q  = t & 7;
    const int e0 = ep * 2;
    const int e1 = e0 + 1;

    unsigned int s0 = (unsigned int)__ldg(&src[e0]);
    unsigned int d0 = (unsigned int)__ldg(&dst[e0]);
    unsigned int s1 = (unsigned int)__ldg(&src[e1]);
    unsigned int d1 = (unsigned int)__ldg(&dst[e1]);
    if (s0 >= N_NODES) s0 = 0;
    if (d0 >= N_NODES) d0 = 0;
    if (s1 >= N_NODES) s1 = 0;
    if (d1 >= N_NODES) d1 = 0;

    uint4 p0 = *(const uint4*)&g_PQh[(size_t)s0 * NOUT + q * 8];
    uint4 r0 = *(const uint4*)&g_PQh[(size_t)d0 * NOUT + 64 + q * 8];
    uint4 p1 = *(const uint4*)&g_PQh[(size_t)s1 * NOUT + q * 8];
    uint4 r1 = *(const uint4*)&g_PQh[(size_t)d1 * NOUT + 64 + q * 8];

    float o0[8], o1[8];
    {
        const __half2* ph = (const __half2*)&p0;
        const __half2* qh = (const __half2*)&r0;
        #pragma unroll
        for (int i = 0; i < 4; ++i) {
            float2 a = __half22float2(ph[i]);
            float2 c = __half22float2(qh[i]);
            o0[i * 2] = a.x + c.x; o0[i * 2 + 1] = a.y + c.y;
        }
    }
    {
        const __half2* ph = (const __half2*)&p1;
        const __half2* qh = (const __half2*)&r1;
        #pragma unroll
        for (int i = 0; i < 4; ++i) {
            float2 a = __half22float2(ph[i]);
            float2 c = __half22float2(qh[i]);
            o1[i * 2] = a.x + c.x; o1[i * 2 + 1] = a.y + c.y;
        }
    }

    float* op0 = out + (size_t)e0 * 64 + q * 8;
    float* op1 = out + (size_t)e1 * 64 + q * 8;
    __stcs((float4*)op0,     make_float4(o0[0], o0[1], o0[2], o0[3]));
    __stcs((float4*)op0 + 1, make_float4(o0[4], o0[5], o0[6], o0[7]));
    __stcs((float4*)op1,     make_float4(o1[0], o1[1], o1[2], o1[3]));
    __stcs((float4*)op1 + 1, make_float4(o1[4], o1[5], o1[6], o1[7]));
}

// ---------------------------------------------------------------------------
extern "C" void kernel_launch(void* const* d_in, const int* in_sizes, int n_in,
                              void* d_out, int out_size) {
    const float* h   = (const float*)d_in[0];
    const int*   src = (const int*)  d_in[1];
    const int*   dst = (const int*)  d_in[2];
    const float* W   = (const float*)d_in[3];
    const float* b   = (const float*)d_in[4];
    float* out = (float*)d_out;

    cudaFuncSetAttribute(gemm_kernel, cudaFuncAttributeMaxDynamicSharedMemorySize, SM_TOTAL);

    gemm_kernel<<<GRIDX, 256, SM_TOTAL>>>(h, W, b);

    const int gthreads = (N_EDGES / 2) * 8;   // 2.4M
    gather_kernel<<<(gthreads + 255) / 256, 256>>>(src, dst, out);
}

// round 11
// speedup vs baseline: 1.0935x; 1.0935x over previous
#include <cuda_runtime.h>
#include <cuda_fp16.h>
#include <cstdint>

#define N_NODES   100000
#define N_EDGES   600000
#define D_FEAT    128
#define NOUT      128          // 64 (P = h@Wu^T + b) + 64 (Q = h@Wv^T)
#define GRIDX     148
#define TILES     782          // ceil(N_NODES / 128)

// ---------------------------------------------------------------------------
// Device scratch: per-node projections in fp16.
// ---------------------------------------------------------------------------
__device__ __half g_PQh[(size_t)N_NODES * NOUT];

// Swizzled byte offset inside a [row][k] fp16 tile with 256B row stride.
__device__ __forceinline__ uint32_t tswz(int row, int kbyte) {
    return (uint32_t)(row * 256 + (kbyte ^ ((row & 7) << 4)));
}

__device__ __forceinline__ uint32_t smem_u32(const void* p) {
    uint32_t a;
    asm("{ .reg .u64 t; cvta.to.shared.u64 t, %1; cvt.u32.u64 %0, t; }" : "=r"(a) : "l"(p));
    return a;
}

__device__ __forceinline__ void ldsm_x4(uint32_t addr, uint32_t* r) {
    asm volatile("ldmatrix.sync.aligned.m8n8.x4.shared.b16 {%0,%1,%2,%3}, [%4];"
                 : "=r"(r[0]), "=r"(r[1]), "=r"(r[2]), "=r"(r[3]) : "r"(addr));
}
__device__ __forceinline__ void ldsm_x2(uint32_t addr, uint32_t* r) {
    asm volatile("ldmatrix.sync.aligned.m8n8.x2.shared.b16 {%0,%1}, [%2];"
                 : "=r"(r[0]), "=r"(r[1]) : "r"(addr));
}
__device__ __forceinline__ void mma_f16(float* c, const uint32_t* a, const uint32_t* b) {
    asm volatile("mma.sync.aligned.m16n8k16.row.col.f32.f16.f16.f32 "
                 "{%0,%1,%2,%3}, {%4,%5,%6,%7}, {%8,%9}, {%0,%1,%2,%3};"
                 : "+f"(c[0]), "+f"(c[1]), "+f"(c[2]), "+f"(c[3])
                 : "r"(a[0]), "r"(a[1]), "r"(a[2]), "r"(a[3]), "r"(b[0]), "r"(b[1]));
}

// Convert float4 -> 2x half2 and store 8B at swizzled offset.
__device__ __forceinline__ void f16_store(char* smem, uint32_t base,
                                          int row, int k4, float4 v) {
    __half2 h0 = __floats2half2_rn(v.x, v.y);
    __half2 h1 = __floats2half2_rn(v.z, v.w);
    uint32_t off = tswz(row, k4 * 8);
    *(uint2*)(smem + base + off) = make_uint2(*(uint32_t*)&h0, *(uint32_t*)&h1);
}

// ---------------------------------------------------------------------------
// Smem: B once (fp16), A double-buffered (fp16). 96 KB, 1 CTA/SM.
// ---------------------------------------------------------------------------
#define SM_B     0u
#define SM_A0    32768u
#define SM_A1    65536u
#define SM_TOTAL 98304

// ---------------------------------------------------------------------------
// Kernel 1: persistent HMMA GEMM (R6 configuration — best measured).
// fp16 single-pass, fp32 accumulate. 148 CTAs x 256 threads, 128x128 tile,
// W staged once, A double-buffered with register prefetch.
// Signals PDL dependents on entering the final tile.
// ---------------------------------------------------------------------------
__global__ void __launch_bounds__(256, 1)
gemm_kernel(const float* __restrict__ h, const float* __restrict__ W,
            const float* __restrict__ b) {
    extern __shared__ char smem[];
    const uint32_t sm_base = smem_u32(smem);
    const int tid = threadIdx.x;
    const int wid = tid >> 5;
    const int lid = tid & 31;

    // ---- Stage B once
    #pragma unroll
    for (int i = tid; i < 4096; i += 256) {
        int j  = i >> 5;
        int k4 = i & 31;
        const float* wp = (j < 64) ? &W[j * 256 + k4 * 4]
                                   : &W[(j - 64) * 256 + 128 + k4 * 4];
        f16_store(smem, SM_B, j, k4, *(const float4*)wp);
    }

    // ---- Stage A first tile into buf0
    {
        const int node0 = blockIdx.x * 128;
        #pragma unroll
        for (int i = 0; i < 16; ++i) {
            int idx = tid + i * 256;
            int m = idx >> 5, k4 = idx & 31;
            int gm = node0 + m; if (gm >= N_NODES) gm = N_NODES - 1;
            float4 v = *(const float4*)&h[(size_t)gm * D_FEAT + k4 * 4];
            f16_store(smem, SM_A0, m, k4, v);
        }
    }
    __syncthreads();

    const int wm = wid & 1;
    const int wn = wid >> 1;
    const int a_row = (lid & 7) + ((lid >> 3) & 1) * 8;
    const int a_kb  = (lid >> 4) * 16;
    const int b_row = (lid & 7);
    const int b_kb  = ((lid >> 3) & 1) * 16;
    const int xora  = (lid & 7) << 4;
    const int trow = lid >> 2;
    const int tcol = (lid & 3) * 2;

    float2 bias2[4];
    #pragma unroll
    for (int nf = 0; nf < 4; ++nf) {
        int col = wn * 32 + nf * 8 + tcol;
        bias2[nf] = (col < 64) ? *(const float2*)&b[col] : make_float2(0.f, 0.f);
    }

    int pb = 0;
    for (int t = blockIdx.x; t < TILES; t += GRIDX, pb ^= 1) {
        const int tn = t + GRIDX;
        const bool pre = (tn < TILES);

        // Entering final tile: allow dependent (gather) grid to start launching.
        if (!pre) asm volatile("griddepcontrol.launch_dependents;");

        float4 regs[16];
        if (pre) {
            const int node0n = tn * 128;
            #pragma unroll
            for (int i = 0; i < 16; ++i) {
                int idx = tid + i * 256;
                int m = idx >> 5, k4 = idx & 31;
                int gm = node0n + m; if (gm >= N_NODES) gm = N_NODES - 1;
                regs[i] = *(const float4*)&h[(size_t)gm * D_FEAT + k4 * 4];
            }
        }

        const uint32_t abase = sm_base + (pb ? SM_A1 : SM_A0);
        float acc[4][4][4];
        #pragma unroll
        for (int mf = 0; mf < 4; ++mf)
            #pragma unroll
            for (int nf = 0; nf < 4; ++nf)
                #pragma unroll
                for (int i = 0; i < 4; ++i) acc[mf][nf][i] = 0.0f;

        #pragma unroll
        for (int ks = 0; ks < 8; ++ks) {
            uint32_t af[4][4], bf[4][2];
            const uint32_t akoff = (uint32_t)((ks * 32 + a_kb) ^ xora);
            const uint32_t bkoff = (uint32_t)((ks * 32 + b_kb) ^ xora);
            #pragma unroll
            for (int mf = 0; mf < 4; ++mf) {
                uint32_t ro = (uint32_t)((wm * 64 + mf * 16 + a_row) * 256) + akoff;
                ldsm_x4(abase + ro, af[mf]);
            }
            #pragma unroll
            for (int nf = 0; nf < 4; ++nf) {
                uint32_t ro = (uint32_t)((wn * 32 + nf * 8 + b_row) * 256) + bkoff;
                ldsm_x2(sm_base + SM_B + ro, bf[nf]);
            }
            #pragma unroll
            for (int mf = 0; mf < 4; ++mf)
                #pragma unroll
                for (int nf = 0; nf < 4; ++nf)
                    mma_f16(acc[mf][nf], af[mf], bf[nf]);
        }

        if (pre) {
            const uint32_t obuf = pb ? SM_A0 : SM_A1;
            #pragma unroll
            for (int i = 0; i < 16; ++i) {
                int idx = tid + i * 256;
                int m = idx >> 5, k4 = idx & 31;
                f16_store(smem, obuf, m, k4, regs[i]);
            }
        }

        const int node0 = t * 128;
        #pragma unroll
        for (int mf = 0; mf < 4; ++mf) {
            const int node_a = node0 + wm * 64 + mf * 16 + trow;
            const int node_b = node_a + 8;
            #pragma unroll
            for (int nf = 0; nf < 4; ++nf) {
                const int col = wn * 32 + nf * 8 + tcol;
                if (node_a < N_NODES) {
                    __half2 hv = __floats2half2_rn(acc[mf][nf][0] + bias2[nf].x,
                                                   acc[mf][nf][1] + bias2[nf].y);
                    *(__half2*)&g_PQh[(size_t)node_a * NOUT + col] = hv;
                }
                if (node_b < N_NODES) {
                    __half2 hv = __floats2half2_rn(acc[mf][nf][2] + bias2[nf].x,
                                                   acc[mf][nf][3] + bias2[nf].y);
                    *(__half2*)&g_PQh[(size_t)node_b * NOUT + col] = hv;
                }
            }
        }
        __syncthreads();
    }
}

// ---------------------------------------------------------------------------
// Kernel 2: gather-add, 2 edges per thread, PDL-overlapped prologue.
// Index loads (no PQ dependency) issue before griddepcontrol.wait; PQ reads
// start the moment the GEMM grid completes.
// out[e][c] = PQh[src[e]][c] + PQh[dst[e]][64+c]
// ---------------------------------------------------------------------------
__global__ void __launch_bounds__(256)
gather_kernel(const int* __restrict__ src, const int* __restrict__ dst,
              float* __restrict__ out) {
    int t = blockIdx.x * blockDim.x + threadIdx.x;
    if (t >= (N_EDGES / 2) * 8) {
        asm volatile("griddepcontrol.wait;" ::: "memory");
        return;
    }
    const int ep = t >> 3;
    const int q  = t & 7;
    const int e0 = ep * 2;

    // Prologue: index loads — independent of GEMM output.
    int2 sv = __ldg((const int2*)&src[e0]);
    int2 dv = __ldg((const int2*)&dst[e0]);
    unsigned int s0 = (unsigned int)sv.x, s1 = (unsigned int)sv.y;
    unsigned int d0 = (unsigned int)dv.x, d1 = (unsigned int)dv.y;
    if (s0 >= N_NODES) s0 = 0;
    if (d0 >= N_NODES) d0 = 0;
    if (s1 >= N_NODES) s1 = 0;
    if (d1 >= N_NODES) d1 = 0;

    // Block until the GEMM grid's PQ writes are visible.
    asm volatile("griddepcontrol.wait;" ::: "memory");

    uint4 p0 = *(const uint4*)&g_PQh[(size_t)s0 * NOUT + q * 8];
    uint4 r0 = *(const uint4*)&g_PQh[(size_t)d0 * NOUT + 64 + q * 8];
    uint4 p1 = *(const uint4*)&g_PQh[(size_t)s1 * NOUT + q * 8];
    uint4 r1 = *(const uint4*)&g_PQh[(size_t)d1 * NOUT + 64 + q * 8];

    float o0[8], o1[8];
    {
        const __half2* ph = (const __half2*)&p0;
        const __half2* qh = (const __half2*)&r0;
        #pragma unroll
        for (int i = 0; i < 4; ++i) {
            float2 a = __half22float2(ph[i]);
            float2 c = __half22float2(qh[i]);
            o0[i * 2] = a.x + c.x; o0[i * 2 + 1] = a.y + c.y;
        }
    }
    {
        const __half2* ph = (const __half2*)&p1;
        const __half2* qh = (const __half2*)&r1;
        #pragma unroll
        for (int i = 0; i < 4; ++i) {
            float2 a = __half22float2(ph[i]);
            float2 c = __half22float2(qh[i]);
            o1[i * 2] = a.x + c.x; o1[i * 2 + 1] = a.y + c.y;
        }
    }

    float* op0 = out + (size_t)e0 * 64 + q * 8;
    float* op1 = op0 + 64;
    __stcs((float4*)op0,     make_float4(o0[0], o0[1], o0[2], o0[3]));
    __stcs((float4*)op0 + 1, make_float4(o0[4], o0[5], o0[6], o0[7]));
    __stcs((float4*)op1,     make_float4(o1[0], o1[1], o1[2], o1[3]));
    __stcs((float4*)op1 + 1, make_float4(o1[4], o1[5], o1[6], o1[7]));
}

// ---------------------------------------------------------------------------
extern "C" void kernel_launch(void* const* d_in, const int* in_sizes, int n_in,
                              void* d_out, int out_size) {
    const float* h   = (const float*)d_in[0];
    const int*   src = (const int*)  d_in[1];
    const int*   dst = (const int*)  d_in[2];
    const float* W   = (const float*)d_in[3];
    const float* b   = (const float*)d_in[4];
    float* out = (float*)d_out;

    cudaFuncSetAttribute(gemm_kernel, cudaFuncAttributeMaxDynamicSharedMemorySize, SM_TOTAL);

    gemm_kernel<<<GRIDX, 256, SM_TOTAL>>>(h, W, b);

    // Gather launched with programmatic dependent launch: its prologue
    // (index loads) overlaps the GEMM tail; griddepcontrol.wait gates PQ reads.
    const int gthreads = (N_EDGES / 2) * 8;   // 2.4M
    cudaLaunchConfig_t cfg = {};
    cfg.gridDim  = dim3((gthreads + 255) / 256);
    cfg.blockDim = dim3(256);
    cfg.dynamicSmemBytes = 0;
    cfg.stream = 0;
    cudaLaunchAttribute attr[1];
    attr[0].id = cudaLaunchAttributeProgrammaticStreamSerialization;
    attr[0].val.programmaticStreamSerializationAllowed = 1;
    cfg.attrs = attr;
    cfg.numAttrs = 1;
    cudaLaunchKernelEx(&cfg, gather_kernel, src, dst, out);
}

// round 12
// speedup vs baseline: 1.1228x; 1.0267x over previous
#include <cuda_runtime.h>
#include <cuda_fp16.h>
#include <cstdint>

#define N_NODES   100000
#define N_EDGES   600000
#define D_FEAT    128
#define NOUT      128          // 64 (P = h@Wu^T + b) + 64 (Q = h@Wv^T)
#define GRIDX     148
#define TILES     782          // ceil(N_NODES / 128)

// ---------------------------------------------------------------------------
// Device scratch: per-node projections in fp16, stored SWIZZLED:
// byte for (node, col) = node*256 + ((col*2) ^ ((node & 7) << 4)).
// The gather applies the same XOR on its 16B-chunk index.
// ---------------------------------------------------------------------------
__device__ __align__(256) __half g_PQh[(size_t)N_NODES * NOUT];

// Swizzled byte offset inside a [row][k] fp16 tile with 256B row stride.
__device__ __forceinline__ uint32_t tswz(int row, int kbyte) {
    return (uint32_t)(row * 256 + (kbyte ^ ((row & 7) << 4)));
}

__device__ __forceinline__ uint32_t smem_u32(const void* p) {
    uint32_t a;
    asm("{ .reg .u64 t; cvta.to.shared.u64 t, %1; cvt.u32.u64 %0, t; }" : "=r"(a) : "l"(p));
    return a;
}

__device__ __forceinline__ void ldsm_x4(uint32_t addr, uint32_t* r) {
    asm volatile("ldmatrix.sync.aligned.m8n8.x4.shared.b16 {%0,%1,%2,%3}, [%4];"
                 : "=r"(r[0]), "=r"(r[1]), "=r"(r[2]), "=r"(r[3]) : "r"(addr));
}
__device__ __forceinline__ void ldsm_x2(uint32_t addr, uint32_t* r) {
    asm volatile("ldmatrix.sync.aligned.m8n8.x2.shared.b16 {%0,%1}, [%2];"
                 : "=r"(r[0]), "=r"(r[1]) : "r"(addr));
}
__device__ __forceinline__ void mma_f16(float* c, const uint32_t* a, const uint32_t* b) {
    asm volatile("mma.sync.aligned.m16n8k16.row.col.f32.f16.f16.f32 "
                 "{%0,%1,%2,%3}, {%4,%5,%6,%7}, {%8,%9}, {%0,%1,%2,%3};"
                 : "+f"(c[0]), "+f"(c[1]), "+f"(c[2]), "+f"(c[3])
                 : "r"(a[0]), "r"(a[1]), "r"(a[2]), "r"(a[3]), "r"(b[0]), "r"(b[1]));
}

// Convert float4 -> 2x half2 and store 8B at swizzled offset.
__device__ __forceinline__ void f16_store(char* smem, uint32_t base,
                                          int row, int k4, float4 v) {
    __half2 h0 = __floats2half2_rn(v.x, v.y);
    __half2 h1 = __floats2half2_rn(v.z, v.w);
    uint32_t off = tswz(row, k4 * 8);
    *(uint2*)(smem + base + off) = make_uint2(*(uint32_t*)&h0, *(uint32_t*)&h1);
}

// ---------------------------------------------------------------------------
// Smem: B once (fp16), A double-buffered (fp16). 96 KB, 1 CTA/SM.
// The dead MMA buffer doubles as the PQ epilogue staging tile (32 KB).
// ---------------------------------------------------------------------------
#define SM_B     0u
#define SM_A0    32768u
#define SM_A1    65536u
#define SM_TOTAL 98304

// ---------------------------------------------------------------------------
// Kernel 1: persistent HMMA GEMM (R6 config) + bulk-store epilogue.
// fp16 single-pass, fp32 accumulate. 148 CTAs x 256 threads, 128x128 tile.
// Epilogue: bias+cvt -> swizzled STS into the dead A buffer -> one
// cp.async.bulk (32 KB) to g_PQh. Stores bypass L1, fully coalesced.
// ---------------------------------------------------------------------------
__global__ void __launch_bounds__(256, 1)
gemm_kernel(const float* __restrict__ h, const float* __restrict__ W,
            const float* __restrict__ b) {
    extern __shared__ char smem[];
    const uint32_t sm_base = smem_u32(smem);
    const int tid = threadIdx.x;
    const int wid = tid >> 5;
    const int lid = tid & 31;

    // ---- Stage B once
    #pragma unroll
    for (int i = tid; i < 4096; i += 256) {
        int j  = i >> 5;
        int k4 = i & 31;
        const float* wp = (j < 64) ? &W[j * 256 + k4 * 4]
                                   : &W[(j - 64) * 256 + 128 + k4 * 4];
        f16_store(smem, SM_B, j, k4, *(const float4*)wp);
    }

    // ---- Stage A first tile into buf0
    {
        const int node0 = blockIdx.x * 128;
        #pragma unroll
        for (int i = 0; i < 16; ++i) {
            int idx = tid + i * 256;
            int m = idx >> 5, k4 = idx & 31;
            int gm = node0 + m; if (gm >= N_NODES) gm = N_NODES - 1;
            float4 v = *(const float4*)&h[(size_t)gm * D_FEAT + k4 * 4];
            f16_store(smem, SM_A0, m, k4, v);
        }
    }
    __syncthreads();

    const int wm = wid & 1;
    const int wn = wid >> 1;
    const int a_row = (lid & 7) + ((lid >> 3) & 1) * 8;
    const int a_kb  = (lid >> 4) * 16;
    const int b_row = (lid & 7);
    const int b_kb  = ((lid >> 3) & 1) * 16;
    const int xora  = (lid & 7) << 4;
    const int trow = lid >> 2;        // 0..7
    const int tcol = (lid & 3) * 2;

    float2 bias2[4];
    #pragma unroll
    for (int nf = 0; nf < 4; ++nf) {
        int col = wn * 32 + nf * 8 + tcol;
        bias2[nf] = (col < 64) ? *(const float2*)&b[col] : make_float2(0.f, 0.f);
    }

    int pb = 0;
    for (int t = blockIdx.x; t < TILES; t += GRIDX, pb ^= 1) {
        const int tn = t + GRIDX;
        const bool pre = (tn < TILES);

        // Entering final tile: allow dependent (gather) grid to start launching.
        if (!pre) asm volatile("griddepcontrol.launch_dependents;");

        // ---- (1) Prefetch next tile's h into registers
        float4 regs[16];
        if (pre) {
            const int node0n = tn * 128;
            #pragma unroll
            for (int i = 0; i < 16; ++i) {
                int idx = tid + i * 256;
                int m = idx >> 5, k4 = idx & 31;
                int gm = node0n + m; if (gm >= N_NODES) gm = N_NODES - 1;
                regs[i] = *(const float4*)&h[(size_t)gm * D_FEAT + k4 * 4];
            }
        }

        // ---- (2) MMA mainloop on buffer pb
        const uint32_t abase = sm_base + (pb ? SM_A1 : SM_A0);
        float acc[4][4][4];
        #pragma unroll
        for (int mf = 0; mf < 4; ++mf)
            #pragma unroll
            for (int nf = 0; nf < 4; ++nf)
                #pragma unroll
                for (int i = 0; i < 4; ++i) acc[mf][nf][i] = 0.0f;

        #pragma unroll
        for (int ks = 0; ks < 8; ++ks) {
            uint32_t af[4][4], bf[4][2];
            const uint32_t akoff = (uint32_t)((ks * 32 + a_kb) ^ xora);
            const uint32_t bkoff = (uint32_t)((ks * 32 + b_kb) ^ xora);
            #pragma unroll
            for (int mf = 0; mf < 4; ++mf) {
                uint32_t ro = (uint32_t)((wm * 64 + mf * 16 + a_row) * 256) + akoff;
                ldsm_x4(abase + ro, af[mf]);
            }
            #pragma unroll
            for (int nf = 0; nf < 4; ++nf) {
                uint32_t ro = (uint32_t)((wn * 32 + nf * 8 + b_row) * 256) + bkoff;
                ldsm_x2(sm_base + SM_B + ro, bf[nf]);
            }
            #pragma unroll
            for (int mf = 0; mf < 4; ++mf)
                #pragma unroll
                for (int nf = 0; nf < 4; ++nf)
                    mma_f16(acc[mf][nf], af[mf], bf[nf]);
        }

        // ---- (3) Drain previous tile's bulk store (it reads buf[pb^1], which
        //          we are about to overwrite), then sync: abase reads done too.
        if (tid == 0) asm volatile("cp.async.bulk.wait_group 0;" ::: "memory");
        __syncthreads();

        // ---- (4) Stage next A tile into buf[pb^1]
        if (pre) {
            const uint32_t obuf = pb ? SM_A0 : SM_A1;
            #pragma unroll
            for (int i = 0; i < 16; ++i) {
                int idx = tid + i * 256;
                int m = idx >> 5, k4 = idx & 31;
                f16_store(smem, obuf, m, k4, regs[i]);
            }
        }

        // ---- (5) Epilogue: bias + cvt, swizzled STS into dead buffer buf[pb].
        //          Swizzle keyed by (row & 7) == trow -> conflict-free banks.
        {
            char* pq = smem + (pb ? SM_A1 : SM_A0);
            const uint32_t key = (uint32_t)trow << 4;
            #pragma unroll
            for (int mf = 0; mf < 4; ++mf) {
                const int ra = wm * 64 + mf * 16 + trow;   // row within tile
                #pragma unroll
                for (int nf = 0; nf < 4; ++nf) {
                    const int col = wn * 32 + nf * 8 + tcol;
                    __half2 h0 = __floats2half2_rn(acc[mf][nf][0] + bias2[nf].x,
                                                   acc[mf][nf][1] + bias2[nf].y);
                    __half2 h1 = __floats2half2_rn(acc[mf][nf][2] + bias2[nf].x,
                                                   acc[mf][nf][3] + bias2[nf].y);
                    uint32_t co = ((uint32_t)(col * 2)) ^ key;
                    *(__half2*)(pq + ra * 256 + co)       = h0;
                    *(__half2*)(pq + (ra + 8) * 256 + co) = h1;
                }
            }
        }
        __syncthreads();

        // ---- (6) One bulk store: smem PQ tile -> g_PQh (contiguous span)
        if (tid == 0) {
            const int node0 = t * 128;
            int rows = N_NODES - node0; if (rows > 128) rows = 128;
            asm volatile("fence.proxy.async.shared::cta;" ::: "memory");
            char* gdst = (char*)g_PQh + (size_t)node0 * 256;
            const uint32_t ssrc = sm_base + (pb ? SM_A1 : SM_A0);
            const uint32_t bytes = (uint32_t)rows * 256u;
            asm volatile("cp.async.bulk.global.shared::cta.bulk_group [%0], [%1], %2;"
                         :: "l"(gdst), "r"(ssrc), "r"(bytes) : "memory");
            asm volatile("cp.async.bulk.commit_group;" ::: "memory");
        }
        // No sync needed here: buf[pb] is not touched until its wait in (3)
        // two iterations later; buf[pb^1] already holds the next A tile.
    }

    // Drain the final bulk store before the grid retires.
    if (tid == 0) asm volatile("cp.async.bulk.wait_group 0;" ::: "memory");
}

// ---------------------------------------------------------------------------
// Kernel 2: gather-add, 2 edges per thread, PDL prologue. Reads the swizzled
// PQ layout: chunk byte = (q*16) ^ ((node & 7) << 4) within each half-row.
// out[e][c] = P[src[e]][c] + Q[dst[e]][c]
// ---------------------------------------------------------------------------
__global__ void __launch_bounds__(256)
gather_kernel(const int* __restrict__ src, const int* __restrict__ dst,
              float* __restrict__ out) {
    int t = blockIdx.x * blockDim.x + threadIdx.x;
    if (t >= (N_EDGES / 2) * 8) {
        asm volatile("griddepcontrol.wait;" ::: "memory");
        return;
    }
    const int ep = t >> 3;
    const int q  = t & 7;
    const int e0 = ep * 2;

    // Prologue: index loads — independent of GEMM output.
    int2 sv = __ldg((const int2*)&src[e0]);
    int2 dv = __ldg((const int2*)&dst[e0]);
    unsigned int s0 = (unsigned int)sv.x, s1 = (unsigned int)sv.y;
    unsigned int d0 = (unsigned int)dv.x, d1 = (unsigned int)dv.y;
    if (s0 >= N_NODES) s0 = 0;
    if (d0 >= N_NODES) d0 = 0;
    if (s1 >= N_NODES) s1 = 0;
    if (d1 >= N_NODES) d1 = 0;

    asm volatile("griddepcontrol.wait;" ::: "memory");

    const char* pqb = (const char*)g_PQh;
    const uint32_t qb = (uint32_t)q * 16u;
    uint4 p0 = *(const uint4*)(pqb + (size_t)s0 * 256 +        (qb ^ ((s0 & 7u) << 4)));
    uint4 r0 = *(const uint4*)(pqb + (size_t)d0 * 256 + 128u + (qb ^ ((d0 & 7u) << 4)));
    uint4 p1 = *(const uint4*)(pqb + (size_t)s1 * 256 +        (qb ^ ((s1 & 7u) << 4)));
    uint4 r1 = *(const uint4*)(pqb + (size_t)d1 * 256 + 128u + (qb ^ ((d1 & 7u) << 4)));

    float o0[8], o1[8];
    {
        const __half2* ph = (const __half2*)&p0;
        const __half2* qh = (const __half2*)&r0;
        #pragma unroll
        for (int i = 0; i < 4; ++i) {
            float2 a = __half22float2(ph[i]);
            float2 c = __half22float2(qh[i]);
            o0[i * 2] = a.x + c.x; o0[i * 2 + 1] = a.y + c.y;
        }
    }
    {
        const __half2* ph = (const __half2*)&p1;
        const __half2* qh = (const __half2*)&r1;
        #pragma unroll
        for (int i = 0; i < 4; ++i) {
            float2 a = __half22float2(ph[i]);
            float2 c = __half22float2(qh[i]);
            o1[i * 2] = a.x + c.x; o1[i * 2 + 1] = a.y + c.y;
        }
    }

    float* op0 = out + (size_t)e0 * 64 + q * 8;
    float* op1 = op0 + 64;
    __stcs((float4*)op0,     make_float4(o0[0], o0[1], o0[2], o0[3]));
    __stcs((float4*)op0 + 1, make_float4(o0[4], o0[5], o0[6], o0[7]));
    __stcs((float4*)op1,     make_float4(o1[0], o1[1], o1[2], o1[3]));
    __stcs((float4*)op1 + 1, make_float4(o1[4], o1[5], o1[6], o1[7]));
}

// ---------------------------------------------------------------------------
extern "C" void kernel_launch(void* const* d_in, const int* in_sizes, int n_in,
                              void* d_out, int out_size) {
    const float* h   = (const float*)d_in[0];
    const int*   src = (const int*)  d_in[1];
    const int*   dst = (const int*)  d_in[2];
    const float* W   = (const float*)d_in[3];
    const float* b   = (const float*)d_in[4];
    float* out = (float*)d_out;

    cudaFuncSetAttribute(gemm_kernel, cudaFuncAttributeMaxDynamicSharedMemorySize, SM_TOTAL);

    gemm_kernel<<<GRIDX, 256, SM_TOTAL>>>(h, W, b);

    const int gthreads = (N_EDGES / 2) * 8;   // 2.4M
    cudaLaunchConfig_t cfg = {};
    cfg.gridDim  = dim3((gthreads + 255) / 256);
    cfg.blockDim = dim3(256);
    cfg.dynamicSmemBytes = 0;
    cfg.stream = 0;
    cudaLaunchAttribute attr[1];
    attr[0].id = cudaLaunchAttributeProgrammaticStreamSerialization;
    attr[0].val.programmaticStreamSerializationAllowed = 1;
    cfg.attrs = attr;
    cfg.numAttrs = 1;
    cudaLaunchKernelEx(&cfg, gather_kernel, src, dst, out);
}

// round 13
// speedup vs baseline: 1.4013x; 1.2481x over previous
#include <cuda_runtime.h>
#include <cuda_fp16.h>
#include <cstdint>

#define N_NODES   100000
#define N_EDGES   600000
#define D_FEAT    128
#define NOUT      128          // 64 (P = h@Wu^T + b) + 64 (Q = h@Wv^T)
#define GRIDX     148
#define TILES     782          // ceil(N_NODES / 128)

// ---------------------------------------------------------------------------
// Device scratch: per-node projections in fp16, stored SWIZZLED:
// byte for (node, col) = node*256 + ((col*2) ^ ((node & 7) << 4)).
// ---------------------------------------------------------------------------
__device__ __align__(256) __half g_PQh[(size_t)N_NODES * NOUT];

// Swizzled byte offset inside a [row][k] fp16 tile with 256B row stride.
__device__ __forceinline__ uint32_t tswz(int row, int kbyte) {
    return (uint32_t)(row * 256 + (kbyte ^ ((row & 7) << 4)));
}

__device__ __forceinline__ uint32_t smem_u32(const void* p) {
    uint32_t a;
    asm("{ .reg .u64 t; cvta.to.shared.u64 t, %1; cvt.u32.u64 %0, t; }" : "=r"(a) : "l"(p));
    return a;
}

__device__ __forceinline__ void ldsm_x4(uint32_t addr, uint32_t* r) {
    asm volatile("ldmatrix.sync.aligned.m8n8.x4.shared.b16 {%0,%1,%2,%3}, [%4];"
                 : "=r"(r[0]), "=r"(r[1]), "=r"(r[2]), "=r"(r[3]) : "r"(addr));
}
__device__ __forceinline__ void ldsm_x2(uint32_t addr, uint32_t* r) {
    asm volatile("ldmatrix.sync.aligned.m8n8.x2.shared.b16 {%0,%1}, [%2];"
                 : "=r"(r[0]), "=r"(r[1]) : "r"(addr));
}
__device__ __forceinline__ void mma_f16(float* c, const uint32_t* a, const uint32_t* b) {
    asm volatile("mma.sync.aligned.m16n8k16.row.col.f32.f16.f16.f32 "
                 "{%0,%1,%2,%3}, {%4,%5,%6,%7}, {%8,%9}, {%0,%1,%2,%3};"
                 : "+f"(c[0]), "+f"(c[1]), "+f"(c[2]), "+f"(c[3])
                 : "r"(a[0]), "r"(a[1]), "r"(a[2]), "r"(a[3]), "r"(b[0]), "r"(b[1]));
}

// Convert float4 -> 2x half2 and store 8B at swizzled offset.
__device__ __forceinline__ void f16_store(char* smem, uint32_t base,
                                          int row, int k4, float4 v) {
    __half2 h0 = __floats2half2_rn(v.x, v.y);
    __half2 h1 = __floats2half2_rn(v.z, v.w);
    uint32_t off = tswz(row, k4 * 8);
    *(uint2*)(smem + base + off) = make_uint2(*(uint32_t*)&h0, *(uint32_t*)&h1);
}

// ---------------------------------------------------------------------------
// Smem: B once (fp16), A double-buffered (fp16). 96 KB, 1 CTA/SM.
// The dead MMA buffer doubles as the PQ epilogue staging tile (32 KB).
// ---------------------------------------------------------------------------
#define SM_B     0u
#define SM_A0    32768u
#define SM_A1    65536u
#define SM_TOTAL 98304

// ---------------------------------------------------------------------------
// Kernel 1: persistent HMMA GEMM + bulk-store epilogue (R12 — unchanged).
// ---------------------------------------------------------------------------
__global__ void __launch_bounds__(256, 1)
gemm_kernel(const float* __restrict__ h, const float* __restrict__ W,
            const float* __restrict__ b) {
    extern __shared__ char smem[];
    const uint32_t sm_base = smem_u32(smem);
    const int tid = threadIdx.x;
    const int wid = tid >> 5;
    const int lid = tid & 31;

    // ---- Stage B once
    #pragma unroll
    for (int i = tid; i < 4096; i += 256) {
        int j  = i >> 5;
        int k4 = i & 31;
        const float* wp = (j < 64) ? &W[j * 256 + k4 * 4]
                                   : &W[(j - 64) * 256 + 128 + k4 * 4];
        f16_store(smem, SM_B, j, k4, *(const float4*)wp);
    }

    // ---- Stage A first tile into buf0
    {
        const int node0 = blockIdx.x * 128;
        #pragma unroll
        for (int i = 0; i < 16; ++i) {
            int idx = tid + i * 256;
            int m = idx >> 5, k4 = idx & 31;
            int gm = node0 + m; if (gm >= N_NODES) gm = N_NODES - 1;
            float4 v = *(const float4*)&h[(size_t)gm * D_FEAT + k4 * 4];
            f16_store(smem, SM_A0, m, k4, v);
        }
    }
    __syncthreads();

    const int wm = wid & 1;
    const int wn = wid >> 1;
    const int a_row = (lid & 7) + ((lid >> 3) & 1) * 8;
    const int a_kb  = (lid >> 4) * 16;
    const int b_row = (lid & 7);
    const int b_kb  = ((lid >> 3) & 1) * 16;
    const int xora  = (lid & 7) << 4;
    const int trow = lid >> 2;        // 0..7
    const int tcol = (lid & 3) * 2;

    float2 bias2[4];
    #pragma unroll
    for (int nf = 0; nf < 4; ++nf) {
        int col = wn * 32 + nf * 8 + tcol;
        bias2[nf] = (col < 64) ? *(const float2*)&b[col] : make_float2(0.f, 0.f);
    }

    int pb = 0;
    for (int t = blockIdx.x; t < TILES; t += GRIDX, pb ^= 1) {
        const int tn = t + GRIDX;
        const bool pre = (tn < TILES);

        if (!pre) asm volatile("griddepcontrol.launch_dependents;");

        // ---- (1) Prefetch next tile's h into registers
        float4 regs[16];
        if (pre) {
            const int node0n = tn * 128;
            #pragma unroll
            for (int i = 0; i < 16; ++i) {
                int idx = tid + i * 256;
                int m = idx >> 5, k4 = idx & 31;
                int gm = node0n + m; if (gm >= N_NODES) gm = N_NODES - 1;
                regs[i] = *(const float4*)&h[(size_t)gm * D_FEAT + k4 * 4];
            }
        }

        // ---- (2) MMA mainloop on buffer pb
        const uint32_t abase = sm_base + (pb ? SM_A1 : SM_A0);
        float acc[4][4][4];
        #pragma unroll
        for (int mf = 0; mf < 4; ++mf)
            #pragma unroll
            for (int nf = 0; nf < 4; ++nf)
                #pragma unroll
                for (int i = 0; i < 4; ++i) acc[mf][nf][i] = 0.0f;

        #pragma unroll
        for (int ks = 0; ks < 8; ++ks) {
            uint32_t af[4][4], bf[4][2];
            const uint32_t akoff = (uint32_t)((ks * 32 + a_kb) ^ xora);
            const uint32_t bkoff = (uint32_t)((ks * 32 + b_kb) ^ xora);
            #pragma unroll
            for (int mf = 0; mf < 4; ++mf) {
                uint32_t ro = (uint32_t)((wm * 64 + mf * 16 + a_row) * 256) + akoff;
                ldsm_x4(abase + ro, af[mf]);
            }
            #pragma unroll
            for (int nf = 0; nf < 4; ++nf) {
                uint32_t ro = (uint32_t)((wn * 32 + nf * 8 + b_row) * 256) + bkoff;
                ldsm_x2(sm_base + SM_B + ro, bf[nf]);
            }
            #pragma unroll
            for (int mf = 0; mf < 4; ++mf)
                #pragma unroll
                for (int nf = 0; nf < 4; ++nf)
                    mma_f16(acc[mf][nf], af[mf], bf[nf]);
        }

        // ---- (3) Drain previous bulk store, then sync
        if (tid == 0) asm volatile("cp.async.bulk.wait_group 0;" ::: "memory");
        __syncthreads();

        // ---- (4) Stage next A tile into buf[pb^1]
        if (pre) {
            const uint32_t obuf = pb ? SM_A0 : SM_A1;
            #pragma unroll
            for (int i = 0; i < 16; ++i) {
                int idx = tid + i * 256;
                int m = idx >> 5, k4 = idx & 31;
                f16_store(smem, obuf, m, k4, regs[i]);
            }
        }

        // ---- (5) Epilogue: bias + cvt, swizzled STS into dead buffer buf[pb]
        {
            char* pq = smem + (pb ? SM_A1 : SM_A0);
            const uint32_t key = (uint32_t)trow << 4;
            #pragma unroll
            for (int mf = 0; mf < 4; ++mf) {
                const int ra = wm * 64 + mf * 16 + trow;
                #pragma unroll
                for (int nf = 0; nf < 4; ++nf) {
                    const int col = wn * 32 + nf * 8 + tcol;
                    __half2 h0 = __floats2half2_rn(acc[mf][nf][0] + bias2[nf].x,
                                                   acc[mf][nf][1] + bias2[nf].y);
                    __half2 h1 = __floats2half2_rn(acc[mf][nf][2] + bias2[nf].x,
                                                   acc[mf][nf][3] + bias2[nf].y);
                    uint32_t co = ((uint32_t)(col * 2)) ^ key;
                    *(__half2*)(pq + ra * 256 + co)       = h0;
                    *(__half2*)(pq + (ra + 8) * 256 + co) = h1;
                }
            }
        }
        __syncthreads();

        // ---- (6) One bulk store: smem PQ tile -> g_PQh
        if (tid == 0) {
            const int node0 = t * 128;
            int rows = N_NODES - node0; if (rows > 128) rows = 128;
            asm volatile("fence.proxy.async.shared::cta;" ::: "memory");
            char* gdst = (char*)g_PQh + (size_t)node0 * 256;
            const uint32_t ssrc = sm_base + (pb ? SM_A1 : SM_A0);
            const uint32_t bytes = (uint32_t)rows * 256u;
            asm volatile("cp.async.bulk.global.shared::cta.bulk_group [%0], [%1], %2;"
                         :: "l"(gdst), "r"(ssrc), "r"(bytes) : "memory");
            asm volatile("cp.async.bulk.commit_group;" ::: "memory");
        }
    }

    if (tid == 0) asm volatile("cp.async.bulk.wait_group 0;" ::: "memory");
}

// ---------------------------------------------------------------------------
// Kernel 2: gather-add, coalesced-store mapping.
// Warp covers 8 consecutive edges. Thread (p = lane>>4, c = lane&15) owns
// out cols 4c..4c+3 (one 16B chunk) of edges eb..eb+3 (eb = warp*8 + 4p).
// Loads: 8B of P + 8B of Q per edge (16 lanes span a full 128B row -> 2 lines
// per LDG). Stores: each STG.128 covers two contiguous 256B runs (4 wf, min).
// out[e][c] = P[src[e]][c] + Q[dst[e]][c]
// ---------------------------------------------------------------------------
__global__ void __launch_bounds__(256)
gather_kernel(const int* __restrict__ src, const int* __restrict__ dst,
              float* __restrict__ out) {
    const int t    = blockIdx.x * 256 + threadIdx.x;
    const int lane = t & 31;
    const int c    = lane & 15;                       // 16B out chunk
    const int eb   = (t >> 5) * 8 + (lane >> 4) * 4;  // first of 4 edges

    // Prologue: index loads — independent of GEMM output (PDL overlap).
    int4 sv = __ldg((const int4*)&src[eb]);
    int4 dv = __ldg((const int4*)&dst[eb]);
    unsigned sa[4] = {(unsigned)sv.x, (unsigned)sv.y, (unsigned)sv.z, (unsigned)sv.w};
    unsigned da[4] = {(unsigned)dv.x, (unsigned)dv.y, (unsigned)dv.z, (unsigned)dv.w};
    #pragma unroll
    for (int k = 0; k < 4; ++k) {
        if (sa[k] >= N_NODES) sa[k] = 0;
        if (da[k] >= N_NODES) da[k] = 0;
    }

    asm volatile("griddepcontrol.wait;" ::: "memory");

    const char* pqb = (const char*)g_PQh;
    const uint32_t chi = (uint32_t)(c >> 1) << 4;   // 16B-chunk offset (pre-swizzle)
    const uint32_t clo = (uint32_t)(c & 1) * 8;     // 8B half within chunk

    // Issue all 8 PQ loads first (max MLP), then compute + store.
    uint2 pv[4], qv[4];
    #pragma unroll
    for (int k = 0; k < 4; ++k) {
        pv[k] = *(const uint2*)(pqb + (size_t)sa[k] * 256 +
                                ((chi ^ ((sa[k] & 7u) << 4)) + clo));
        qv[k] = *(const uint2*)(pqb + (size_t)da[k] * 256 + 128u +
                                ((chi ^ ((da[k] & 7u) << 4)) + clo));
    }

    #pragma unroll
    for (int k = 0; k < 4; ++k) {
        float2 a0 = __half22float2(*(__half2*)&pv[k].x);
        float2 a1 = __half22float2(*(__half2*)&pv[k].y);
        float2 b0 = __half22float2(*(__half2*)&qv[k].x);
        float2 b1 = __half22float2(*(__half2*)&qv[k].y);
        float4 o = make_float4(a0.x + b0.x, a0.y + b0.y, a1.x + b1.x, a1.y + b1.y);
        __stcs((float4*)((char*)out + (size_t)(eb + k) * 256 + (uint32_t)c * 16), o);
    }
}

// ---------------------------------------------------------------------------
extern "C" void kernel_launch(void* const* d_in, const int* in_sizes, int n_in,
                              void* d_out, int out_size) {
    const float* h   = (const float*)d_in[0];
    const int*   src = (const int*)  d_in[1];
    const int*   dst = (const int*)  d_in[2];
    const float* W   = (const float*)d_in[3];
    const float* b   = (const float*)d_in[4];
    float* out = (float*)d_out;

    cudaFuncSetAttribute(gemm_kernel, cudaFuncAttributeMaxDynamicSharedMemorySize, SM_TOTAL);

    gemm_kernel<<<GRIDX, 256, SM_TOTAL>>>(h, W, b);

    // 75000 warps x 8 edges = 600000 edges; grid exact, no tail.
    const int gthreads = (N_EDGES / 8) * 32;   // 2.4M
    cudaLaunchConfig_t cfg = {};
    cfg.gridDim  = dim3(gthreads / 256);       // 9375
    cfg.blockDim = dim3(256);
    cfg.dynamicSmemBytes = 0;
    cfg.stream = 0;
    cudaLaunchAttribute attr[1];
    attr[0].id = cudaLaunchAttributeProgrammaticStreamSerialization;
    attr[0].val.programmaticStreamSerializationAllowed = 1;
    cfg.attrs = attr;
    cfg.numAttrs = 1;
    cudaLaunchKernelEx(&cfg, gather_kernel, src, dst, out);
}